// round 4
// baseline (speedup 1.0000x reference)
#include <cuda_runtime.h>
#include <math.h>

#define Hh    1024
#define Ii    512
#define TWOI  1024
#define Ee    64
#define TT    8192
#define CAPc  1024

// ---------------- scratch (static device globals; allocation-free) ----------
__device__ int   g_cnt[Ee];
__device__ int   g_tok[Ee * CAPc];
__device__ int   g_slot[TT * 2];
__device__ int   g_eid[TT * 2];
__device__ float g_wt[TT * 2];
__device__ float g_xn[(size_t)TT * Hh];                  // 32 MB
__device__ float g_hact[(size_t)Ee * CAPc * Ii];         // 128 MB
__device__ float g_ybuf[(size_t)Ee * CAPc * Hh];         // 256 MB
__device__ float g_shact[(size_t)TT * Ii];               // 16 MB
__device__ float g_shout[(size_t)TT * Hh];               // 32 MB

// ---------------- kernel 0: zero expert counters ----------------------------
__global__ void k_zero() {
    if (threadIdx.x < Ee) g_cnt[threadIdx.x] = 0;
}

// ---------------- kernel 1: rmsnorm + gate logits + top2 + routing ----------
__global__ void k_rms_route(const float* __restrict__ hs,
                            const float* __restrict__ rmsw,
                            const float* __restrict__ gw) {
    __shared__ float xs[Hh];
    __shared__ float lg[Ee];
    __shared__ float red[8];
    const int t   = blockIdx.x;
    const int tid = threadIdx.x;
    const float* hrow = hs + (size_t)t * Hh;

    float ss = 0.f;
    for (int i = tid; i < Hh; i += 256) { float v = hrow[i]; xs[i] = v; ss += v * v; }
    #pragma unroll
    for (int o = 16; o; o >>= 1) ss += __shfl_xor_sync(0xffffffffu, ss, o);
    if ((tid & 31) == 0) red[tid >> 5] = ss;
    __syncthreads();
    if (tid < 8) {
        float v = red[tid];
        #pragma unroll
        for (int o = 4; o; o >>= 1) v += __shfl_xor_sync(0xffu, v, o);
        if (tid == 0) red[0] = v;
    }
    __syncthreads();
    const float scale = rsqrtf(red[0] * (1.0f / Hh) + 1e-6f);
    for (int i = tid; i < Hh; i += 256) {
        float v = xs[i] * scale * rmsw[i];
        xs[i] = v;
        g_xn[(size_t)t * Hh + i] = v;
    }
    __syncthreads();

    // gate logits: 8 warps x 8 experts each
    const int w = tid >> 5, lane = tid & 31;
    #pragma unroll
    for (int j = 0; j < 8; j++) {
        const int e = w * 8 + j;
        const float* ge = gw + (size_t)e * Hh;
        float s = 0.f;
        for (int i = lane; i < Hh; i += 32) s += xs[i] * ge[i];
        #pragma unroll
        for (int o = 16; o; o >>= 1) s += __shfl_xor_sync(0xffffffffu, s, o);
        if (lane == 0) lg[e] = s;
    }
    __syncthreads();

    if (tid == 0) {
        float l1 = -1e30f, l2 = -1e30f; int e1 = 0, e2 = 0;
        #pragma unroll
        for (int e = 0; e < Ee; e++) {
            float v = lg[e];
            if (v > l1)      { l2 = l1; e2 = e1; l1 = v; e1 = e; }
            else if (v > l2) { l2 = v;  e2 = e; }
        }
        // renormalized top-2 weights == softmax over the two top logits
        const float w1 = 1.f / (1.f + expf(l2 - l1));
        const float w2 = 1.f - w1;
        g_eid[2 * t] = e1; g_eid[2 * t + 1] = e2;
        g_wt [2 * t] = w1; g_wt [2 * t + 1] = w2;
        int s1 = atomicAdd(&g_cnt[e1], 1);
        int s2 = atomicAdd(&g_cnt[e2], 1);
        if (s1 < CAPc) { g_tok[e1 * CAPc + s1] = t; g_slot[2 * t]     = s1; }
        else           { g_slot[2 * t]     = -1; }
        if (s2 < CAPc) { g_tok[e2 * CAPc + s2] = t; g_slot[2 * t + 1] = s2; }
        else           { g_slot[2 * t + 1] = -1; }
    }
}

// ---------------- kernel 2: expert GEMM1 (gather + gu + silu-glu) -----------
// 64x64 output tile per block (g and u columns together), 256 threads, 4x4 micro.
__global__ void k_eg1(const float* __restrict__ w13) {
    const int e = blockIdx.x;
    const int cnt = min(g_cnt[e], CAPc);
    const int row0 = blockIdx.y << 6;
    if (row0 >= cnt) return;
    const int col0 = blockIdx.z << 6;           // within [0, Ii)

    __shared__ float  As[16][68];
    __shared__ float4 Bg[16][16];
    __shared__ float4 Bu[16][16];
    __shared__ int    toks[64];

    const int tid = threadIdx.x;
    if (tid < 64) {
        int r = row0 + tid;
        toks[tid] = (r < cnt) ? g_tok[e * CAPc + r] : -1;
    }
    __syncthreads();

    const int lm  = tid >> 2;                 // A-load row 0..63
    const int lk4 = (tid & 3) << 2;           // A-load k-sub 0,4,8,12
    const int bk  = tid >> 4;                 // B-load k 0..15
    const int bn  = tid & 15;                 // B-load n4
    const int tm  = tid >> 4, tn = tid & 15;  // compute micro-tile coords

    const float* wg = w13 + (size_t)e * Hh * TWOI + col0;
    const float* wu = wg + Ii;
    const int atok = toks[lm];
    const float* aptr = (atok >= 0) ? (g_xn + (size_t)atok * Hh + lk4) : nullptr;

    float accg[4][4] = {}, accu[4][4] = {};

    for (int k0 = 0; k0 < Hh; k0 += 16) {
        float4 av = aptr ? *(const float4*)(aptr + k0) : make_float4(0.f, 0.f, 0.f, 0.f);
        float4 bgv = *(const float4*)(wg + (size_t)(k0 + bk) * TWOI + (bn << 2));
        float4 buv = *(const float4*)(wu + (size_t)(k0 + bk) * TWOI + (bn << 2));
        As[lk4 + 0][lm] = av.x; As[lk4 + 1][lm] = av.y;
        As[lk4 + 2][lm] = av.z; As[lk4 + 3][lm] = av.w;
        Bg[bk][bn] = bgv; Bu[bk][bn] = buv;
        __syncthreads();
        #pragma unroll
        for (int k = 0; k < 16; k++) {
            const float4 a  = *(const float4*)&As[k][tm << 2];
            const float4 bg = Bg[k][tn];
            const float4 bu = Bu[k][tn];
            const float am[4]  = {a.x, a.y, a.z, a.w};
            const float bgm[4] = {bg.x, bg.y, bg.z, bg.w};
            const float bum[4] = {bu.x, bu.y, bu.z, bu.w};
            #pragma unroll
            for (int i = 0; i < 4; i++)
                #pragma unroll
                for (int j = 0; j < 4; j++) {
                    accg[i][j] += am[i] * bgm[j];
                    accu[i][j] += am[i] * bum[j];
                }
        }
        __syncthreads();
    }

    float* out = g_hact + (size_t)e * CAPc * Ii;
    #pragma unroll
    for (int i = 0; i < 4; i++) {
        const int r = row0 + (tm << 2) + i;
        float4 v;
        float* vp = &v.x;
        #pragma unroll
        for (int j = 0; j < 4; j++) {
            const float g = accg[i][j];
            vp[j] = g / (1.f + expf(-g)) * accu[i][j];   // silu(g) * u
        }
        *(float4*)(out + (size_t)r * Ii + col0 + (tn << 2)) = v;
    }
}

// ---------------- kernel 3: expert GEMM2 (down-proj into ybuf) --------------
__global__ void k_eg2(const float* __restrict__ w2) {
    const int e = blockIdx.x;
    const int cnt = min(g_cnt[e], CAPc);
    const int row0 = blockIdx.y << 6;
    if (row0 >= cnt) return;
    const int col0 = blockIdx.z << 6;           // within [0, Hh)

    __shared__ float  As[16][68];
    __shared__ float4 Bs[16][16];

    const int tid = threadIdx.x;
    const int lm  = tid >> 2;
    const int lk4 = (tid & 3) << 2;
    const int bk  = tid >> 4;
    const int bn  = tid & 15;
    const int tm  = tid >> 4, tn = tid & 15;

    const float* aptr = g_hact + (size_t)e * CAPc * Ii + (size_t)(row0 + lm) * Ii + lk4;
    const float* bptr = w2 + (size_t)e * Ii * Hh + col0;

    float acc[4][4] = {};
    for (int k0 = 0; k0 < Ii; k0 += 16) {
        float4 av = *(const float4*)(aptr + k0);
        float4 bv = *(const float4*)(bptr + (size_t)(k0 + bk) * Hh + (bn << 2));
        As[lk4 + 0][lm] = av.x; As[lk4 + 1][lm] = av.y;
        As[lk4 + 2][lm] = av.z; As[lk4 + 3][lm] = av.w;
        Bs[bk][bn] = bv;
        __syncthreads();
        #pragma unroll
        for (int k = 0; k < 16; k++) {
            const float4 a = *(const float4*)&As[k][tm << 2];
            const float4 b = Bs[k][tn];
            const float am[4] = {a.x, a.y, a.z, a.w};
            const float bm[4] = {b.x, b.y, b.z, b.w};
            #pragma unroll
            for (int i = 0; i < 4; i++)
                #pragma unroll
                for (int j = 0; j < 4; j++) acc[i][j] += am[i] * bm[j];
        }
        __syncthreads();
    }

    float* out = g_ybuf + (size_t)e * CAPc * Hh;
    #pragma unroll
    for (int i = 0; i < 4; i++) {
        const int r = row0 + (tm << 2) + i;
        float4 v = make_float4(acc[i][0], acc[i][1], acc[i][2], acc[i][3]);
        *(float4*)(out + (size_t)r * Hh + col0 + (tn << 2)) = v;
    }
}

// ---------------- kernel 4: shared expert GEMM1 (gu + silu-glu) -------------
__global__ void k_sg1(const float* __restrict__ swg, const float* __restrict__ swu) {
    const int row0 = blockIdx.x << 6;
    const int col0 = blockIdx.y << 6;           // within [0, Ii)

    __shared__ float  As[16][68];
    __shared__ float4 Bg[16][16];
    __shared__ float4 Bu[16][16];

    const int tid = threadIdx.x;
    const int lm  = tid >> 2;
    const int lk4 = (tid & 3) << 2;
    const int bk  = tid >> 4;
    const int bn  = tid & 15;
    const int tm  = tid >> 4, tn = tid & 15;

    const float* aptr = g_xn + (size_t)(row0 + lm) * Hh + lk4;
    const float* wg = swg + col0;
    const float* wu = swu + col0;

    float accg[4][4] = {}, accu[4][4] = {};
    for (int k0 = 0; k0 < Hh; k0 += 16) {
        float4 av  = *(const float4*)(aptr + k0);
        float4 bgv = *(const float4*)(wg + (size_t)(k0 + bk) * Ii + (bn << 2));
        float4 buv = *(const float4*)(wu + (size_t)(k0 + bk) * Ii + (bn << 2));
        As[lk4 + 0][lm] = av.x; As[lk4 + 1][lm] = av.y;
        As[lk4 + 2][lm] = av.z; As[lk4 + 3][lm] = av.w;
        Bg[bk][bn] = bgv; Bu[bk][bn] = buv;
        __syncthreads();
        #pragma unroll
        for (int k = 0; k < 16; k++) {
            const float4 a  = *(const float4*)&As[k][tm << 2];
            const float4 bg = Bg[k][tn];
            const float4 bu = Bu[k][tn];
            const float am[4]  = {a.x, a.y, a.z, a.w};
            const float bgm[4] = {bg.x, bg.y, bg.z, bg.w};
            const float bum[4] = {bu.x, bu.y, bu.z, bu.w};
            #pragma unroll
            for (int i = 0; i < 4; i++)
                #pragma unroll
                for (int j = 0; j < 4; j++) {
                    accg[i][j] += am[i] * bgm[j];
                    accu[i][j] += am[i] * bum[j];
                }
        }
        __syncthreads();
    }

    #pragma unroll
    for (int i = 0; i < 4; i++) {
        const int r = row0 + (tm << 2) + i;
        float4 v;
        float* vp = &v.x;
        #pragma unroll
        for (int j = 0; j < 4; j++) {
            const float g = accg[i][j];
            vp[j] = g / (1.f + expf(-g)) * accu[i][j];
        }
        *(float4*)(g_shact + (size_t)r * Ii + col0 + (tn << 2)) = v;
    }
}

// ---------------- kernel 5: shared expert GEMM2 -----------------------------
__global__ void k_sg2(const float* __restrict__ swd) {
    const int row0 = blockIdx.x << 6;
    const int col0 = blockIdx.y << 6;           // within [0, Hh)

    __shared__ float  As[16][68];
    __shared__ float4 Bs[16][16];

    const int tid = threadIdx.x;
    const int lm  = tid >> 2;
    const int lk4 = (tid & 3) << 2;
    const int bk  = tid >> 4;
    const int bn  = tid & 15;
    const int tm  = tid >> 4, tn = tid & 15;

    const float* aptr = g_shact + (size_t)(row0 + lm) * Ii + lk4;
    const float* bptr = swd + col0;

    float acc[4][4] = {};
    for (int k0 = 0; k0 < Ii; k0 += 16) {
        float4 av = *(const float4*)(aptr + k0);
        float4 bv = *(const float4*)(bptr + (size_t)(k0 + bk) * Hh + (bn << 2));
        As[lk4 + 0][lm] = av.x; As[lk4 + 1][lm] = av.y;
        As[lk4 + 2][lm] = av.z; As[lk4 + 3][lm] = av.w;
        Bs[bk][bn] = bv;
        __syncthreads();
        #pragma unroll
        for (int k = 0; k < 16; k++) {
            const float4 a = *(const float4*)&As[k][tm << 2];
            const float4 b = Bs[k][tn];
            const float am[4] = {a.x, a.y, a.z, a.w};
            const float bm[4] = {b.x, b.y, b.z, b.w};
            #pragma unroll
            for (int i = 0; i < 4; i++)
                #pragma unroll
                for (int j = 0; j < 4; j++) acc[i][j] += am[i] * bm[j];
        }
        __syncthreads();
    }

    #pragma unroll
    for (int i = 0; i < 4; i++) {
        const int r = row0 + (tm << 2) + i;
        float4 v = make_float4(acc[i][0], acc[i][1], acc[i][2], acc[i][3]);
        *(float4*)(g_shout + (size_t)r * Hh + col0 + (tn << 2)) = v;
    }
}

// ---------------- kernel 6: combine: residual + shared + sum_k w*y ----------
__global__ void k_comb(const float* __restrict__ hs, float* __restrict__ out) {
    const int t = blockIdx.x;
    const int tid = threadIdx.x;
    const int e0 = g_eid[2 * t], e1 = g_eid[2 * t + 1];
    const int s0 = g_slot[2 * t], s1 = g_slot[2 * t + 1];
    const float w0 = g_wt[2 * t], w1 = g_wt[2 * t + 1];

    const float4* r4  = (const float4*)(hs + (size_t)t * Hh);
    const float4* sh4 = (const float4*)(g_shout + (size_t)t * Hh);
    const float4* y0  = (s0 >= 0) ? (const float4*)(g_ybuf + ((size_t)e0 * CAPc + s0) * Hh) : nullptr;
    const float4* y1  = (s1 >= 0) ? (const float4*)(g_ybuf + ((size_t)e1 * CAPc + s1) * Hh) : nullptr;
    float4* o4 = (float4*)(out + (size_t)t * Hh);

    for (int i = tid; i < Hh / 4; i += 256) {
        float4 a = r4[i], b = sh4[i];
        float4 acc = make_float4(a.x + b.x, a.y + b.y, a.z + b.z, a.w + b.w);
        if (y0) { float4 y = y0[i]; acc.x += w0 * y.x; acc.y += w0 * y.y; acc.z += w0 * y.z; acc.w += w0 * y.w; }
        if (y1) { float4 y = y1[i]; acc.x += w1 * y.x; acc.y += w1 * y.y; acc.z += w1 * y.z; acc.w += w1 * y.w; }
        o4[i] = acc;
    }
}

// ---------------- launcher ---------------------------------------------------
extern "C" void kernel_launch(void* const* d_in, const int* in_sizes, int n_in,
                              void* d_out, int out_size) {
    const float* hs   = (const float*)d_in[0];
    const float* rmsw = (const float*)d_in[1];
    const float* gw   = (const float*)d_in[2];
    const float* w13  = (const float*)d_in[3];
    const float* w2   = (const float*)d_in[4];
    const float* swg  = (const float*)d_in[5];
    const float* swu  = (const float*)d_in[6];
    const float* swd  = (const float*)d_in[7];
    float* out = (float*)d_out;

    k_zero<<<1, 64>>>();
    k_rms_route<<<TT, 256>>>(hs, rmsw, gw);
    k_eg1<<<dim3(Ee, CAPc / 64, Ii / 64), 256>>>(w13);
    k_sg1<<<dim3(TT / 64, Ii / 64), 256>>>(swg, swu);
    k_eg2<<<dim3(Ee, CAPc / 64, Hh / 64), 256>>>(w2);
    k_sg2<<<dim3(TT / 64, Hh / 64), 256>>>(swd);
    k_comb<<<TT, 256>>>(hs, out);
}

// round 5
// speedup vs baseline: 1.5010x; 1.5010x over previous
#include <cuda_runtime.h>
#include <cstdint>
#include <math.h>

#define Hh    1024
#define Ii    512
#define TWOI  1024
#define Ee    64
#define TT    8192
#define CAPc  1024
#define KC    32
#define LDA   36
#define LDB   136

// ---------------- scratch (static device globals; allocation-free) ----------
__device__ int   g_cnt[Ee];
__device__ int   g_tok[Ee * CAPc];
__device__ int   g_slot[TT * 2];
__device__ int   g_eid[TT * 2];
__device__ float g_wt[TT * 2];
__device__ float g_xn[(size_t)TT * Hh];
__device__ float g_hact[(size_t)Ee * CAPc * Ii];
__device__ float g_ybuf[(size_t)Ee * CAPc * Hh];
__device__ float g_shact[(size_t)TT * Ii];
__device__ float g_shout[(size_t)TT * Hh];

// ---------------- helpers ----------------------------------------------------
__device__ __forceinline__ uint32_t cvt_tf32(float x) {
    uint32_t r; asm("cvt.rna.tf32.f32 %0, %1;" : "=r"(r) : "f"(x)); return r;
}
__device__ __forceinline__ void mma8(float* d, const uint32_t* a, const uint32_t* b) {
    asm volatile("mma.sync.aligned.m16n8k8.row.col.f32.tf32.tf32.f32 "
                 "{%0,%1,%2,%3},{%4,%5,%6,%7},{%8,%9},{%0,%1,%2,%3};"
                 : "+f"(d[0]), "+f"(d[1]), "+f"(d[2]), "+f"(d[3])
                 : "r"(a[0]), "r"(a[1]), "r"(a[2]), "r"(a[3]), "r"(b[0]), "r"(b[1]));
}
__device__ __forceinline__ void cpa16(void* s, const void* g) {
    uint32_t sa = (uint32_t)__cvta_generic_to_shared(s);
    asm volatile("cp.async.cg.shared.global [%0], [%1], 16;" :: "r"(sa), "l"(g));
}
__device__ __forceinline__ float silu(float x) { return x / (1.f + expf(-x)); }

// ---------------- tf32 tensor-core GEMM tile: 128 rows x 128 tile cols -------
// GLU: tile cols interleave gate/up in 8-col n-tiles (even=gate, odd=up of the
// SAME 8 output cols) so each thread holds matching g/u pairs for the silu.
template<bool GLU, bool GATHER, int KD>
__device__ __forceinline__ void gemm_tile(
    const float* __restrict__ Asrc, int lda,
    const int* __restrict__ gtoks, int cnt, int row0,
    const float* __restrict__ Bg, const float* __restrict__ Bu, int ldb,
    float* __restrict__ C, int ldc)
{
    __shared__ float As[128 * LDA];
    __shared__ float Bs[KC * LDB];
    __shared__ int   toks[128];

    const int tid = threadIdx.x;
    if (GATHER) {
        if (tid < 128) toks[tid] = gtoks[min(row0 + tid, cnt - 1)];
    }
    const int wid = tid >> 5, lane = tid & 31;
    const int wr = wid >> 2, wc = wid & 3;     // warp grid 2x4
    const int qr = lane >> 2, qc = lane & 3;   // quad row/col within warp

    float acc[4][4][4];
    #pragma unroll
    for (int i = 0; i < 4; i++)
        #pragma unroll
        for (int j = 0; j < 4; j++)
            #pragma unroll
            for (int k = 0; k < 4; k++) acc[i][j][k] = 0.f;

    for (int k0 = 0; k0 < KD; k0 += KC) {
        __syncthreads();   // prev-stage compute done (also covers toks on iter 0)
        // ---- load A: 128 rows x 32 k, 16B chunks, swizzle-free padded stride
        #pragma unroll
        for (int j = 0; j < 4; j++) {
            int idx = tid + j * 256;
            int m = idx >> 3, kc = (idx & 7) << 2;
            const float* src = GATHER
                ? Asrc + (size_t)toks[m] * lda + k0 + kc
                : Asrc + (size_t)(row0 + m) * lda + k0 + kc;
            cpa16(&As[m * LDA + kc], src);
        }
        // ---- load B: 32 k x 128 tile cols
        #pragma unroll
        for (int j = 0; j < 4; j++) {
            int idx = tid + j * 256;
            int k = idx >> 5, nc = (idx & 31) << 2;
            const float* src;
            if (GLU) {
                int grp = nc >> 4, off = nc & 15;
                const float* b = (off < 8) ? (Bg + grp * 8 + off)
                                           : (Bu + grp * 8 + off - 8);
                src = b + (size_t)(k0 + k) * ldb;
            } else {
                src = Bg + nc + (size_t)(k0 + k) * ldb;
            }
            cpa16(&Bs[k * LDB + nc], src);
        }
        asm volatile("cp.async.commit_group;\n\tcp.async.wait_group 0;" ::: "memory");
        __syncthreads();

        // ---- compute: 4 k-steps of 8
        #pragma unroll
        for (int ks = 0; ks < KC; ks += 8) {
            uint32_t af[4][4], bf[4][2];
            #pragma unroll
            for (int i = 0; i < 4; i++) {
                int r = wr * 64 + i * 16 + qr;
                af[i][0] = cvt_tf32(As[r * LDA + ks + qc]);
                af[i][1] = cvt_tf32(As[(r + 8) * LDA + ks + qc]);
                af[i][2] = cvt_tf32(As[r * LDA + ks + qc + 4]);
                af[i][3] = cvt_tf32(As[(r + 8) * LDA + ks + qc + 4]);
            }
            #pragma unroll
            for (int j = 0; j < 4; j++) {
                int n = wc * 32 + j * 8 + qr;
                bf[j][0] = cvt_tf32(Bs[(ks + qc) * LDB + n]);
                bf[j][1] = cvt_tf32(Bs[(ks + qc + 4) * LDB + n]);
            }
            #pragma unroll
            for (int i = 0; i < 4; i++)
                #pragma unroll
                for (int j = 0; j < 4; j++) mma8(acc[i][j], af[i], bf[j]);
        }
    }

    // ---- epilogue
    if (GLU) {
        #pragma unroll
        for (int i = 0; i < 4; i++) {
            size_t r = (size_t)(wr * 64 + i * 16 + qr);
            #pragma unroll
            for (int jg = 0; jg < 4; jg += 2) {
                int c = (wc * 2 + (jg >> 1)) * 8 + 2 * qc;
                const float* g = acc[i][jg];
                const float* u = acc[i][jg + 1];
                float2 v0 = make_float2(silu(g[0]) * u[0], silu(g[1]) * u[1]);
                float2 v1 = make_float2(silu(g[2]) * u[2], silu(g[3]) * u[3]);
                *(float2*)(C + r * ldc + c)       = v0;
                *(float2*)(C + (r + 8) * ldc + c) = v1;
            }
        }
    } else {
        #pragma unroll
        for (int i = 0; i < 4; i++) {
            size_t r = (size_t)(wr * 64 + i * 16 + qr);
            #pragma unroll
            for (int j = 0; j < 4; j++) {
                int c = (wc * 4 + j) * 8 + 2 * qc;
                *(float2*)(C + r * ldc + c)       = make_float2(acc[i][j][0], acc[i][j][1]);
                *(float2*)(C + (r + 8) * ldc + c) = make_float2(acc[i][j][2], acc[i][j][3]);
            }
        }
    }
}

// ---------------- GEMM kernels -----------------------------------------------
__global__ void __launch_bounds__(256, 2) k_eg1(const float* __restrict__ w13) {
    const int e = blockIdx.x;
    const int cnt = min(g_cnt[e], CAPc);
    const int row0 = blockIdx.y << 7;
    if (cnt == 0 || row0 >= cnt) return;
    const float* Bg = w13 + (size_t)e * Hh * TWOI + blockIdx.z * 64;
    const float* Bu = Bg + Ii;
    float* C = g_hact + (size_t)e * CAPc * Ii + (size_t)row0 * Ii + blockIdx.z * 64;
    gemm_tile<true, true, Hh>(g_xn, Hh, g_tok + e * CAPc, cnt, row0, Bg, Bu, TWOI, C, Ii);
}

__global__ void __launch_bounds__(256, 2) k_eg2(const float* __restrict__ w2) {
    const int e = blockIdx.x;
    const int cnt = min(g_cnt[e], CAPc);
    const int row0 = blockIdx.y << 7;
    if (cnt == 0 || row0 >= cnt) return;
    const float* B = w2 + (size_t)e * Ii * Hh + blockIdx.z * 128;
    float* C = g_ybuf + (size_t)e * CAPc * Hh + (size_t)row0 * Hh + blockIdx.z * 128;
    gemm_tile<false, false, Ii>(g_hact + (size_t)e * CAPc * Ii, Ii, nullptr, 0, row0,
                                B, nullptr, Hh, C, Hh);
}

__global__ void __launch_bounds__(256, 2) k_sg1(const float* __restrict__ swg,
                                                const float* __restrict__ swu) {
    const int row0 = blockIdx.x << 7;
    const float* Bg = swg + blockIdx.y * 64;
    const float* Bu = swu + blockIdx.y * 64;
    float* C = g_shact + (size_t)row0 * Ii + blockIdx.y * 64;
    gemm_tile<true, false, Hh>(g_xn, Hh, nullptr, 0, row0, Bg, Bu, Ii, C, Ii);
}

__global__ void __launch_bounds__(256, 2) k_sg2(const float* __restrict__ swd) {
    const int row0 = blockIdx.x << 7;
    const float* B = swd + blockIdx.y * 128;
    float* C = g_shout + (size_t)row0 * Hh + blockIdx.y * 128;
    gemm_tile<false, false, Ii>(g_shact, Ii, nullptr, 0, row0, B, nullptr, Hh, C, Hh);
}

// ---------------- kernel 0: zero expert counters ----------------------------
__global__ void k_zero() {
    if (threadIdx.x < Ee) g_cnt[threadIdx.x] = 0;
}

// ---------------- kernel 1: rmsnorm + gate logits + top2 + routing ----------
__global__ void k_rms_route(const float* __restrict__ hs,
                            const float* __restrict__ rmsw,
                            const float* __restrict__ gw) {
    __shared__ float xs[Hh];
    __shared__ float lg[Ee];
    __shared__ float red[8];
    const int t   = blockIdx.x;
    const int tid = threadIdx.x;
    const float* hrow = hs + (size_t)t * Hh;

    float ss = 0.f;
    for (int i = tid; i < Hh; i += 256) { float v = hrow[i]; xs[i] = v; ss += v * v; }
    #pragma unroll
    for (int o = 16; o; o >>= 1) ss += __shfl_xor_sync(0xffffffffu, ss, o);
    if ((tid & 31) == 0) red[tid >> 5] = ss;
    __syncthreads();
    if (tid < 8) {
        float v = red[tid];
        #pragma unroll
        for (int o = 4; o; o >>= 1) v += __shfl_xor_sync(0xffu, v, o);
        if (tid == 0) red[0] = v;
    }
    __syncthreads();
    const float scale = rsqrtf(red[0] * (1.0f / Hh) + 1e-6f);
    for (int i = tid; i < Hh; i += 256) {
        float v = xs[i] * scale * rmsw[i];
        xs[i] = v;
        g_xn[(size_t)t * Hh + i] = v;
    }
    __syncthreads();

    const int w = tid >> 5, lane = tid & 31;
    #pragma unroll
    for (int j = 0; j < 8; j++) {
        const int e = w * 8 + j;
        const float* ge = gw + (size_t)e * Hh;
        float s = 0.f;
        for (int i = lane; i < Hh; i += 32) s += xs[i] * ge[i];
        #pragma unroll
        for (int o = 16; o; o >>= 1) s += __shfl_xor_sync(0xffffffffu, s, o);
        if (lane == 0) lg[e] = s;
    }
    __syncthreads();

    if (tid == 0) {
        float l1 = -1e30f, l2 = -1e30f; int e1 = 0, e2 = 0;
        #pragma unroll
        for (int e = 0; e < Ee; e++) {
            float v = lg[e];
            if (v > l1)      { l2 = l1; e2 = e1; l1 = v; e1 = e; }
            else if (v > l2) { l2 = v;  e2 = e; }
        }
        const float w1 = 1.f / (1.f + expf(l2 - l1));
        const float w2 = 1.f - w1;
        g_eid[2 * t] = e1; g_eid[2 * t + 1] = e2;
        g_wt [2 * t] = w1; g_wt [2 * t + 1] = w2;
        int s1 = atomicAdd(&g_cnt[e1], 1);
        int s2 = atomicAdd(&g_cnt[e2], 1);
        if (s1 < CAPc) { g_tok[e1 * CAPc + s1] = t; g_slot[2 * t]     = s1; }
        else           { g_slot[2 * t]     = -1; }
        if (s2 < CAPc) { g_tok[e2 * CAPc + s2] = t; g_slot[2 * t + 1] = s2; }
        else           { g_slot[2 * t + 1] = -1; }
    }
}

// ---------------- combine: residual + shared + sum_k w*y --------------------
__global__ void k_comb(const float* __restrict__ hs, float* __restrict__ out) {
    const int t = blockIdx.x;
    const int tid = threadIdx.x;
    const int e0 = g_eid[2 * t], e1 = g_eid[2 * t + 1];
    const int s0 = g_slot[2 * t], s1 = g_slot[2 * t + 1];
    const float w0 = g_wt[2 * t], w1 = g_wt[2 * t + 1];

    const float4* r4  = (const float4*)(hs + (size_t)t * Hh);
    const float4* sh4 = (const float4*)(g_shout + (size_t)t * Hh);
    const float4* y0  = (s0 >= 0) ? (const float4*)(g_ybuf + ((size_t)e0 * CAPc + s0) * Hh) : nullptr;
    const float4* y1  = (s1 >= 0) ? (const float4*)(g_ybuf + ((size_t)e1 * CAPc + s1) * Hh) : nullptr;
    float4* o4 = (float4*)(out + (size_t)t * Hh);

    for (int i = tid; i < Hh / 4; i += 256) {
        float4 a = r4[i], b = sh4[i];
        float4 acc = make_float4(a.x + b.x, a.y + b.y, a.z + b.z, a.w + b.w);
        if (y0) { float4 y = y0[i]; acc.x += w0 * y.x; acc.y += w0 * y.y; acc.z += w0 * y.z; acc.w += w0 * y.w; }
        if (y1) { float4 y = y1[i]; acc.x += w1 * y.x; acc.y += w1 * y.y; acc.z += w1 * y.z; acc.w += w1 * y.w; }
        o4[i] = acc;
    }
}

// ---------------- launcher ---------------------------------------------------
extern "C" void kernel_launch(void* const* d_in, const int* in_sizes, int n_in,
                              void* d_out, int out_size) {
    const float* hs   = (const float*)d_in[0];
    const float* rmsw = (const float*)d_in[1];
    const float* gw   = (const float*)d_in[2];
    const float* w13  = (const float*)d_in[3];
    const float* w2   = (const float*)d_in[4];
    const float* swg  = (const float*)d_in[5];
    const float* swu  = (const float*)d_in[6];
    const float* swd  = (const float*)d_in[7];
    float* out = (float*)d_out;

    k_zero<<<1, 64>>>();
    k_rms_route<<<TT, 256>>>(hs, rmsw, gw);
    k_eg1<<<dim3(Ee, CAPc / 128, Ii / 64), 256>>>(w13);
    k_sg1<<<dim3(TT / 128, Ii / 64), 256>>>(swg, swu);
    k_eg2<<<dim3(Ee, CAPc / 128, Hh / 128), 256>>>(w2);
    k_sg2<<<dim3(TT / 128, Hh / 128), 256>>>(swd);
    k_comb<<<TT, 256>>>(hs, out);
}

// round 7
// speedup vs baseline: 2.0828x; 1.3876x over previous
#include <cuda_runtime.h>
#include <cstdint>
#include <math.h>

#define Hh    1024
#define Ii    512
#define TWOI  1024
#define Ee    64
#define TT    8192
#define CAPc  1024
#define KC    32
#define LDA   36
#define LDB   136

#define A_SZ  (128 * LDA)          // floats per A stage buffer
#define B_SZ  (KC * LDB)           // floats per B stage buffer
#define SMEM_FLOATS (2 * A_SZ + 2 * B_SZ + 128)
#define SMEM_BYTES  (SMEM_FLOATS * 4)

// ---------------- scratch (static device globals; allocation-free) ----------
__device__ int   g_cnt[Ee];
__device__ int   g_tok[Ee * CAPc];
__device__ int   g_slot[TT * 2];
__device__ int   g_eid[TT * 2];
__device__ float g_wt[TT * 2];
__device__ float g_xn[(size_t)TT * Hh];
__device__ float g_hact[(size_t)Ee * CAPc * Ii];
__device__ float g_ybuf[(size_t)Ee * CAPc * Hh];
__device__ float g_shact[(size_t)TT * Ii];
__device__ float g_shout[(size_t)TT * Hh];

// ---------------- helpers ----------------------------------------------------
__device__ __forceinline__ uint32_t cvt_tf32(float x) {
    uint32_t r; asm("cvt.rna.tf32.f32 %0, %1;" : "=r"(r) : "f"(x)); return r;
}
__device__ __forceinline__ void mma8(float* d, const uint32_t* a, const uint32_t* b) {
    asm volatile("mma.sync.aligned.m16n8k8.row.col.f32.tf32.tf32.f32 "
                 "{%0,%1,%2,%3},{%4,%5,%6,%7},{%8,%9},{%0,%1,%2,%3};"
                 : "+f"(d[0]), "+f"(d[1]), "+f"(d[2]), "+f"(d[3])
                 : "r"(a[0]), "r"(a[1]), "r"(a[2]), "r"(a[3]), "r"(b[0]), "r"(b[1]));
}
__device__ __forceinline__ void cpa16(float* s, const void* g) {
    uint32_t sa = (uint32_t)__cvta_generic_to_shared(s);
    asm volatile("cp.async.cg.shared.global [%0], [%1], 16;" :: "r"(sa), "l"(g));
}
__device__ __forceinline__ float silu(float x) { return x / (1.f + expf(-x)); }

// ---------------- tf32 tensor-core GEMM tile: 128 rows x 128 tile cols -------
// Double-buffered cp.async pipeline; dynamic smem.
// GLU: tile cols interleave gate/up in 8-col n-tiles so each thread holds
// matching g/u pairs for the silu epilogue.
template<bool GLU, bool GATHER, int KD>
__device__ __forceinline__ void gemm_tile(
    const float* __restrict__ Asrc, int lda,
    const int* __restrict__ gtoks, int cnt, int row0,
    const float* __restrict__ Bg, const float* __restrict__ Bu, int ldb,
    float* __restrict__ C, int ldc)
{
    extern __shared__ float smem[];
    float* AsBuf[2] = { smem,            smem + A_SZ };
    float* BsBuf[2] = { smem + 2 * A_SZ, smem + 2 * A_SZ + B_SZ };
    int*   toks     = (int*)(smem + 2 * A_SZ + 2 * B_SZ);

    const int tid = threadIdx.x;
    if (GATHER) {
        if (tid < 128) toks[tid] = gtoks[min(row0 + tid, cnt - 1)];
        __syncthreads();
    }
    const int wid = tid >> 5, lane = tid & 31;
    const int wr = wid >> 2, wc = wid & 3;     // warp grid 2x4
    const int qr = lane >> 2, qc = lane & 3;   // quad row/col within warp

    // load coordinates
    const int lm  = tid >> 3, lkc = (tid & 7) << 2;    // A: base row (0..31), k-sub
    const int bk  = tid >> 5, bnc = (tid & 31) << 2;   // B: base k (0..7),  n-sub

    // per-j A row pointers: each thread loads rows lm, lm+32, lm+64, lm+96.
    // GATHER must resolve the token for EACH of those rows (R6 bug: used toks[lm] only).
    const float* arow[4];
    #pragma unroll
    for (int j = 0; j < 4; j++) {
        const int m = lm + j * 32;
        arow[j] = GATHER ? Asrc + (size_t)toks[m] * lda + lkc
                         : Asrc + (size_t)(row0 + m) * lda + lkc;
    }
    const float* brow;
    if (GLU) {
        int grp = bnc >> 4, off = bnc & 15;
        brow = (off < 8) ? (Bg + grp * 8 + off) : (Bu + grp * 8 + off - 8);
        brow += (size_t)bk * ldb;
    } else {
        brow = Bg + bnc + (size_t)bk * ldb;
    }

    auto load_stage = [&](int s, int buf) {
        const int k0 = s * KC;
        float* As = AsBuf[buf];
        float* Bs = BsBuf[buf];
        #pragma unroll
        for (int j = 0; j < 4; j++)
            cpa16(&As[(lm + j * 32) * LDA + lkc], arow[j] + k0);
        #pragma unroll
        for (int j = 0; j < 4; j++)
            cpa16(&Bs[(bk + j * 8) * LDB + bnc], brow + (size_t)(k0 + j * 8) * ldb);
        asm volatile("cp.async.commit_group;" ::: "memory");
    };

    float acc[4][4][4];
    #pragma unroll
    for (int i = 0; i < 4; i++)
        #pragma unroll
        for (int j = 0; j < 4; j++)
            #pragma unroll
            for (int k = 0; k < 4; k++) acc[i][j][k] = 0.f;

    constexpr int S = KD / KC;
    load_stage(0, 0);

    for (int s = 0; s < S; s++) {
        const int buf = s & 1;
        if (s + 1 < S) {
            load_stage(s + 1, (s + 1) & 1);
            asm volatile("cp.async.wait_group 1;" ::: "memory");
        } else {
            asm volatile("cp.async.wait_group 0;" ::: "memory");
        }
        __syncthreads();

        const float* As = AsBuf[buf];
        const float* Bs = BsBuf[buf];
        #pragma unroll
        for (int ks = 0; ks < KC; ks += 8) {
            uint32_t af[4][4], bf[4][2];
            #pragma unroll
            for (int i = 0; i < 4; i++) {
                int r = wr * 64 + i * 16 + qr;
                af[i][0] = cvt_tf32(As[r * LDA + ks + qc]);
                af[i][1] = cvt_tf32(As[(r + 8) * LDA + ks + qc]);
                af[i][2] = cvt_tf32(As[r * LDA + ks + qc + 4]);
                af[i][3] = cvt_tf32(As[(r + 8) * LDA + ks + qc + 4]);
            }
            #pragma unroll
            for (int j = 0; j < 4; j++) {
                int n = wc * 32 + j * 8 + qr;
                bf[j][0] = cvt_tf32(Bs[(ks + qc) * LDB + n]);
                bf[j][1] = cvt_tf32(Bs[(ks + qc + 4) * LDB + n]);
            }
            #pragma unroll
            for (int i = 0; i < 4; i++)
                #pragma unroll
                for (int j = 0; j < 4; j++) mma8(acc[i][j], af[i], bf[j]);
        }
        __syncthreads();   // compute done before s+2 overwrites this buffer
    }

    // ---- epilogue
    if (GLU) {
        #pragma unroll
        for (int i = 0; i < 4; i++) {
            size_t r = (size_t)(wr * 64 + i * 16 + qr);
            #pragma unroll
            for (int jg = 0; jg < 4; jg += 2) {
                int c = (wc * 2 + (jg >> 1)) * 8 + 2 * qc;
                const float* g = acc[i][jg];
                const float* u = acc[i][jg + 1];
                *(float2*)(C + r * ldc + c)       = make_float2(silu(g[0]) * u[0], silu(g[1]) * u[1]);
                *(float2*)(C + (r + 8) * ldc + c) = make_float2(silu(g[2]) * u[2], silu(g[3]) * u[3]);
            }
        }
    } else {
        #pragma unroll
        for (int i = 0; i < 4; i++) {
            size_t r = (size_t)(wr * 64 + i * 16 + qr);
            #pragma unroll
            for (int j = 0; j < 4; j++) {
                int c = (wc * 4 + j) * 8 + 2 * qc;
                *(float2*)(C + r * ldc + c)       = make_float2(acc[i][j][0], acc[i][j][1]);
                *(float2*)(C + (r + 8) * ldc + c) = make_float2(acc[i][j][2], acc[i][j][3]);
            }
        }
    }
}

// ---------------- GEMM kernels -----------------------------------------------
__global__ void __launch_bounds__(256, 2) k_eg1(const float* __restrict__ w13) {
    const int e = blockIdx.x;
    const int cnt = min(g_cnt[e], CAPc);
    const int row0 = blockIdx.y << 7;
    if (cnt == 0 || row0 >= cnt) return;
    const float* Bg = w13 + (size_t)e * Hh * TWOI + blockIdx.z * 64;
    const float* Bu = Bg + Ii;
    float* C = g_hact + (size_t)e * CAPc * Ii + (size_t)row0 * Ii + blockIdx.z * 64;
    gemm_tile<true, true, Hh>(g_xn, Hh, g_tok + e * CAPc, cnt, row0, Bg, Bu, TWOI, C, Ii);
}

__global__ void __launch_bounds__(256, 2) k_eg2(const float* __restrict__ w2) {
    const int e = blockIdx.x;
    const int cnt = min(g_cnt[e], CAPc);
    const int row0 = blockIdx.y << 7;
    if (cnt == 0 || row0 >= cnt) return;
    const float* B = w2 + (size_t)e * Ii * Hh + blockIdx.z * 128;
    float* C = g_ybuf + (size_t)e * CAPc * Hh + (size_t)row0 * Hh + blockIdx.z * 128;
    gemm_tile<false, false, Ii>(g_hact + (size_t)e * CAPc * Ii, Ii, nullptr, 0, row0,
                                B, nullptr, Hh, C, Hh);
}

__global__ void __launch_bounds__(256, 2) k_sg1(const float* __restrict__ swg,
                                                const float* __restrict__ swu) {
    const int row0 = blockIdx.x << 7;
    const float* Bg = swg + blockIdx.y * 64;
    const float* Bu = swu + blockIdx.y * 64;
    float* C = g_shact + (size_t)row0 * Ii + blockIdx.y * 64;
    gemm_tile<true, false, Hh>(g_xn, Hh, nullptr, 0, row0, Bg, Bu, Ii, C, Ii);
}

__global__ void __launch_bounds__(256, 2) k_sg2(const float* __restrict__ swd) {
    const int row0 = blockIdx.x << 7;
    const float* B = swd + blockIdx.y * 128;
    float* C = g_shout + (size_t)row0 * Hh + blockIdx.y * 128;
    gemm_tile<false, false, Ii>(g_shact, Ii, nullptr, 0, row0, B, nullptr, Hh, C, Hh);
}

// ---------------- kernel 0: zero expert counters ----------------------------
__global__ void k_zero() {
    if (threadIdx.x < Ee) g_cnt[threadIdx.x] = 0;
}

// ---------------- kernel 1: rmsnorm + gate logits + top2 + routing ----------
__global__ void k_rms_route(const float* __restrict__ hs,
                            const float* __restrict__ rmsw,
                            const float* __restrict__ gw) {
    __shared__ float xs[Hh];
    __shared__ float lg[Ee];
    __shared__ float red[8];
    const int t   = blockIdx.x;
    const int tid = threadIdx.x;
    const float* hrow = hs + (size_t)t * Hh;

    float ss = 0.f;
    for (int i = tid; i < Hh; i += 256) { float v = hrow[i]; xs[i] = v; ss += v * v; }
    #pragma unroll
    for (int o = 16; o; o >>= 1) ss += __shfl_xor_sync(0xffffffffu, ss, o);
    if ((tid & 31) == 0) red[tid >> 5] = ss;
    __syncthreads();
    if (tid < 8) {
        float v = red[tid];
        #pragma unroll
        for (int o = 4; o; o >>= 1) v += __shfl_xor_sync(0xffu, v, o);
        if (tid == 0) red[0] = v;
    }
    __syncthreads();
    const float scale = rsqrtf(red[0] * (1.0f / Hh) + 1e-6f);
    for (int i = tid; i < Hh; i += 256) {
        float v = xs[i] * scale * rmsw[i];
        xs[i] = v;
        g_xn[(size_t)t * Hh + i] = v;
    }
    __syncthreads();

    const int w = tid >> 5, lane = tid & 31;
    #pragma unroll
    for (int j = 0; j < 8; j++) {
        const int e = w * 8 + j;
        const float* ge = gw + (size_t)e * Hh;
        float s = 0.f;
        for (int i = lane; i < Hh; i += 32) s += xs[i] * ge[i];
        #pragma unroll
        for (int o = 16; o; o >>= 1) s += __shfl_xor_sync(0xffffffffu, s, o);
        if (lane == 0) lg[e] = s;
    }
    __syncthreads();

    if (tid == 0) {
        float l1 = -1e30f, l2 = -1e30f; int e1 = 0, e2 = 0;
        #pragma unroll
        for (int e = 0; e < Ee; e++) {
            float v = lg[e];
            if (v > l1)      { l2 = l1; e2 = e1; l1 = v; e1 = e; }
            else if (v > l2) { l2 = v;  e2 = e; }
        }
        const float w1 = 1.f / (1.f + expf(l2 - l1));
        const float w2 = 1.f - w1;
        g_eid[2 * t] = e1; g_eid[2 * t + 1] = e2;
        g_wt [2 * t] = w1; g_wt [2 * t + 1] = w2;
        int s1 = atomicAdd(&g_cnt[e1], 1);
        int s2 = atomicAdd(&g_cnt[e2], 1);
        if (s1 < CAPc) { g_tok[e1 * CAPc + s1] = t; g_slot[2 * t]     = s1; }
        else           { g_slot[2 * t]     = -1; }
        if (s2 < CAPc) { g_tok[e2 * CAPc + s2] = t; g_slot[2 * t + 1] = s2; }
        else           { g_slot[2 * t + 1] = -1; }
    }
}

// ---------------- combine: residual + shared + sum_k w*y --------------------
__global__ void k_comb(const float* __restrict__ hs, float* __restrict__ out) {
    const int t = blockIdx.x;
    const int tid = threadIdx.x;
    const int e0 = g_eid[2 * t], e1 = g_eid[2 * t + 1];
    const int s0 = g_slot[2 * t], s1 = g_slot[2 * t + 1];
    const float w0 = g_wt[2 * t], w1 = g_wt[2 * t + 1];

    const float4* r4  = (const float4*)(hs + (size_t)t * Hh);
    const float4* sh4 = (const float4*)(g_shout + (size_t)t * Hh);
    const float4* y0  = (s0 >= 0) ? (const float4*)(g_ybuf + ((size_t)e0 * CAPc + s0) * Hh) : nullptr;
    const float4* y1  = (s1 >= 0) ? (const float4*)(g_ybuf + ((size_t)e1 * CAPc + s1) * Hh) : nullptr;
    float4* o4 = (float4*)(out + (size_t)t * Hh);

    for (int i = tid; i < Hh / 4; i += 256) {
        float4 a = r4[i], b = sh4[i];
        float4 acc = make_float4(a.x + b.x, a.y + b.y, a.z + b.z, a.w + b.w);
        if (y0) { float4 y = y0[i]; acc.x += w0 * y.x; acc.y += w0 * y.y; acc.z += w0 * y.z; acc.w += w0 * y.w; }
        if (y1) { float4 y = y1[i]; acc.x += w1 * y.x; acc.y += w1 * y.y; acc.z += w1 * y.z; acc.w += w1 * y.w; }
        o4[i] = acc;
    }
}

// ---------------- launcher ---------------------------------------------------
extern "C" void kernel_launch(void* const* d_in, const int* in_sizes, int n_in,
                              void* d_out, int out_size) {
    const float* hs   = (const float*)d_in[0];
    const float* rmsw = (const float*)d_in[1];
    const float* gw   = (const float*)d_in[2];
    const float* w13  = (const float*)d_in[3];
    const float* w2   = (const float*)d_in[4];
    const float* swg  = (const float*)d_in[5];
    const float* swu  = (const float*)d_in[6];
    const float* swd  = (const float*)d_in[7];
    float* out = (float*)d_out;

    // host-side attribute set; idempotent and deterministic (no static guards)
    cudaFuncSetAttribute(k_eg1, cudaFuncAttributeMaxDynamicSharedMemorySize, SMEM_BYTES);
    cudaFuncSetAttribute(k_eg2, cudaFuncAttributeMaxDynamicSharedMemorySize, SMEM_BYTES);
    cudaFuncSetAttribute(k_sg1, cudaFuncAttributeMaxDynamicSharedMemorySize, SMEM_BYTES);
    cudaFuncSetAttribute(k_sg2, cudaFuncAttributeMaxDynamicSharedMemorySize, SMEM_BYTES);

    k_zero<<<1, 64>>>();
    k_rms_route<<<TT, 256>>>(hs, rmsw, gw);
    k_eg1<<<dim3(Ee, CAPc / 128, Ii / 64), 256, SMEM_BYTES>>>(w13);
    k_sg1<<<dim3(TT / 128, Ii / 64), 256, SMEM_BYTES>>>(swg, swu);
    k_eg2<<<dim3(Ee, CAPc / 128, Hh / 128), 256, SMEM_BYTES>>>(w2);
    k_sg2<<<dim3(TT / 128, Hh / 128), 256, SMEM_BYTES>>>(swd);
    k_comb<<<TT, 256>>>(hs, out);
}